// round 4
// baseline (speedup 1.0000x reference)
#include <cuda_runtime.h>
#include <cuda_bf16.h>
#include <cstdint>

#define DIM        4096
#define B          8
#define UP_OUT     1024               // N_KV * HEAD_DIM
#define KSPLIT     4                  // K-chunks for up-projection
#define NCHUNK     4                  // down/broadcast pipeline chunks
#define CCOLS      (DIM / NCHUNK)     // 1024 output columns per chunk
#define TPB_TOK    4                  // tokens per broadcast block

// Scratch (allocation-free rule: __device__ globals)
__device__ float g_xp[KSPLIT][B * UP_OUT]; // up partials [4][8,1024]
__device__ float g_y[B * DIM];             // down result [8,4096]

// ---------------------------------------------------------------------------
// Kernel 1: up GEMV (K-split partials, fully unrolled) + W_down chunk-0
// L2 prefetch riding in extra blocks (up is latency-bound; DRAM is idle).
// Blocks [0,512): compute. Blocks [512,1024): prefetch rows 0..1023 of W_down.
// ---------------------------------------------------------------------------
__global__ __launch_bounds__(256) void up_gemv_pref(const float* __restrict__ emb,
                                                    const float* __restrict__ Wup,
                                                    const float* __restrict__ Wdown) {
    int bid = blockIdx.x;
    if (bid >= 512) {
        // Prefetch chunk 0 of W_down into L2: 512 blocks x 32 KB = 16 MB.
        const float4* p = (const float4*)Wdown + (size_t)(bid - 512) * 2048;
        float s = 0.f;
#pragma unroll
        for (int i = 0; i < 8; i++) {
            float4 v = __ldg(p + i * 256 + threadIdx.x);
            s += v.x + v.y + v.z + v.w;
        }
        asm volatile("" :: "f"(s));   // keep loads live, no store
        return;
    }

    int gw   = (bid * 256 + threadIdx.x) >> 5;  // 0..4095
    int lane = threadIdx.x & 31;
    int j = gw >> 2;                            // output column 0..1023
    int s = gw & 3;                             // K chunk 0..3

    const int CHUNK4 = DIM / 4 / KSPLIT;        // 256 float4
    const float4* wrow = (const float4*)(Wup + (size_t)j * DIM) + s * CHUNK4;
    const float4* e4   = (const float4*)emb + s * CHUNK4;

    float acc[B];
#pragma unroll
    for (int b = 0; b < B; b++) acc[b] = 0.f;

#pragma unroll
    for (int k = 0; k < CHUNK4 / 32; k++) {     // 8 iters, fully unrolled
        int c = k * 32 + lane;
        float4 w = __ldg(&wrow[c]);
#pragma unroll
        for (int b = 0; b < B; b++) {
            float4 e = __ldg(&e4[b * (DIM / 4) + c]);
            acc[b] += e.x * w.x + e.y * w.y + e.z * w.z + e.w * w.w;
        }
    }
#pragma unroll
    for (int b = 0; b < B; b++) {
#pragma unroll
        for (int off = 16; off > 0; off >>= 1)
            acc[b] += __shfl_down_sync(0xffffffffu, acc[b], off);
    }
    if (lane == 0) {
#pragma unroll
        for (int b = 0; b < B; b++) g_xp[s][b * UP_OUT + j] = acc[b];
    }
}

// ---------------------------------------------------------------------------
// Kernel 2 (x4): down GEMV for one 1024-column chunk.
// y[b, o] = sum_i val[b,i] * W_down[o,i],  val[b,i] = x[b, ((i>>9)<<7)|(i&127)].
// sx staged in smem (summing the 4 up partials). Warp per column.
// ---------------------------------------------------------------------------
__global__ __launch_bounds__(256) void down_chunk(const float* __restrict__ Wdown, int g) {
    __shared__ float sx[B * UP_OUT];            // 32 KB
    {
        float4* dst = (float4*)sx;
        for (int i = threadIdx.x; i < B * UP_OUT / 4; i += 256) {
            float4 a = __ldg((const float4*)g_xp[0] + i);
            float4 b = __ldg((const float4*)g_xp[1] + i);
            float4 c = __ldg((const float4*)g_xp[2] + i);
            float4 d = __ldg((const float4*)g_xp[3] + i);
            float4 r;
            r.x = (a.x + b.x) + (c.x + d.x);
            r.y = (a.y + b.y) + (c.y + d.y);
            r.z = (a.z + b.z) + (c.z + d.z);
            r.w = (a.w + b.w) + (c.w + d.w);
            dst[i] = r;
        }
    }
    __syncthreads();

    int warp = (blockIdx.x * 256 + threadIdx.x) >> 5;  // 0..1023 within chunk
    int lane = threadIdx.x & 31;
    int col  = g * CCOLS + warp;

    const float4* wrow = (const float4*)(Wdown + (size_t)col * DIM);
    float acc[B];
#pragma unroll
    for (int b = 0; b < B; b++) acc[b] = 0.f;

#pragma unroll 8
    for (int c = lane; c < DIM / 4; c += 32) {
        float4 w = __ldg(&wrow[c]);
        int i  = c * 4;
        int xi = ((i >> 9) << 7) | (i & 127);   // head -> kv head
#pragma unroll
        for (int b = 0; b < B; b++) {
            float4 v = *(const float4*)(sx + b * UP_OUT + xi);
            acc[b] += v.x * w.x + v.y * w.y + v.z * w.z + v.w * w.w;
        }
    }
#pragma unroll
    for (int b = 0; b < B; b++) {
#pragma unroll
        for (int off = 16; off > 0; off >>= 1)
            acc[b] += __shfl_down_sync(0xffffffffu, acc[b], off);
    }
    if (lane == 0) {
#pragma unroll
        for (int b = 0; b < B; b++) g_y[b * DIM + col] = acc[b];
    }
}

// ---------------------------------------------------------------------------
// Kernel 3 (x4): broadcast one 1024-column chunk of y to all token rows.
// out[t, g*1024 : (g+1)*1024] = y[batch(t), same cols]. 4 tokens per block,
// each thread stores one float4 per token (4 KB contiguous per token-chunk).
// Streaming stores; y chunk is L2-resident.
// ---------------------------------------------------------------------------
__global__ __launch_bounds__(256) void bcast_chunk(float4* __restrict__ out,
                                                   const void* __restrict__ seqlen_raw,
                                                   int total_tokens, int g) {
    __shared__ int sb[TPB_TOK];
    int t0 = blockIdx.x * TPB_TOK;
    if (threadIdx.x < TPB_TOK) {
        const int*       s32 = (const int*)seqlen_raw;
        const long long* s64 = (const long long*)seqlen_raw;
        long long sum64 = 0;
#pragma unroll
        for (int i = 0; i < B; i++) sum64 += s64[i];
        bool use64 = (sum64 == (long long)total_tokens);
        int t = t0 + threadIdx.x;
        int acc = 0, b = 0;
#pragma unroll
        for (int i = 0; i < B; i++) {
            int len = use64 ? (int)s64[i] : s32[i];
            if (t >= acc + len) b = i + 1;
            acc += len;
        }
        sb[threadIdx.x] = (b < B) ? b : (B - 1);
    }
    __syncthreads();

    int c = threadIdx.x;                        // 0..255 float4 within chunk
#pragma unroll
    for (int k = 0; k < TPB_TOK; k++) {
        int t = t0 + k;
        if (t < total_tokens) {
            const float4* yrow = (const float4*)(g_y + (size_t)sb[k] * DIM + g * CCOLS);
            float4*       orow = out + (size_t)t * (DIM / 4) + g * (CCOLS / 4);
            __stcs(orow + c, __ldg(yrow + c));
        }
    }
}

// ---------------------------------------------------------------------------
// Launch: up(+prefetch) -> [ down(g) on main stream | bcast(g) on side stream ]
// pipelined: bcast(g) waits only on down(g), so down(g+1..) overlaps bcast(g).
// Multi-stream fork/join via events (standard cross-stream capture pattern).
// ---------------------------------------------------------------------------
extern "C" void kernel_launch(void* const* d_in, const int* in_sizes, int n_in,
                              void* d_out, int out_size) {
    const float* emb   = (const float*)d_in[0];  // [8, 4096]
    const float* Wup   = (const float*)d_in[1];  // [1024, 4096]
    const float* Wdown = (const float*)d_in[2];  // [4096, 4096]
    const void*  seql  = d_in[3];                // [8] int32 or int64

    int total_tokens = out_size / DIM;           // 16384

    cudaStream_t s1;
    cudaStreamCreateWithFlags(&s1, cudaStreamNonBlocking);
    cudaEvent_t ev[NCHUNK], evEnd;
    for (int g = 0; g < NCHUNK; g++)
        cudaEventCreateWithFlags(&ev[g], cudaEventDisableTiming);
    cudaEventCreateWithFlags(&evEnd, cudaEventDisableTiming);

    up_gemv_pref<<<1024, 256>>>(emb, Wup, Wdown);        // 512 compute + 512 prefetch

    int bgrid = (total_tokens + TPB_TOK - 1) / TPB_TOK;  // 4096
    for (int g = 0; g < NCHUNK; g++) {
        down_chunk<<<CCOLS / 8, 256>>>(Wdown, g);        // 128 blocks, 1024 warps
        cudaEventRecord(ev[g], 0);
        cudaStreamWaitEvent(s1, ev[g], 0);
        bcast_chunk<<<bgrid, 256, 0, s1>>>((float4*)d_out, seql, total_tokens, g);
    }
    cudaEventRecord(evEnd, s1);
    cudaStreamWaitEvent(0, evEnd, 0);                    // join side stream
}

// round 5
// speedup vs baseline: 1.5539x; 1.5539x over previous
#include <cuda_runtime.h>
#include <cuda_bf16.h>
#include <cstdint>

#define DIM        4096
#define B          8
#define UP_OUT     1024               // N_KV * HEAD_DIM
#define KSPLIT     4                  // K-chunks for up-projection

#define UP_BLOCKS   512               // compute blocks in kernel 1
#define PREF_BLOCKS 2048              // prefetch blocks: 2048 x 32 KB = all of W_down

// Scratch (allocation-free rule: __device__ globals)
__device__ float g_xp[KSPLIT][B * UP_OUT]; // up partials [4][8,1024]
__device__ float g_y[B * DIM];             // down result [8,4096]

// ---------------------------------------------------------------------------
// Kernel 1: up GEMV (K-split partials, fully unrolled) + full W_down L2
// prefetch riding in extra blocks. up is latency-bound (DRAM 17% in R3), so
// the prefetch uses otherwise-idle bandwidth; W_down (67 MB) fits in L2
// (~126 MB), making the following down kernel L2-resident.
// Blocks [0,512): compute. Blocks [512,2560): prefetch.
// ---------------------------------------------------------------------------
__global__ __launch_bounds__(256) void up_gemv_pref(const float* __restrict__ emb,
                                                    const float* __restrict__ Wup,
                                                    const float* __restrict__ Wdown) {
    int bid = blockIdx.x;
    if (bid >= UP_BLOCKS) {
        // Pure L2-fill: 256 threads x 8 float4 = 32 KB per block.
        const float4* p = (const float4*)Wdown + (size_t)(bid - UP_BLOCKS) * 2048;
        float s = 0.f;
#pragma unroll
        for (int i = 0; i < 8; i++) {
            float4 v = __ldg(p + i * 256 + threadIdx.x);
            s += v.x + v.y + v.z + v.w;
        }
        asm volatile("" :: "f"(s));   // keep loads live
        return;
    }

    int gw   = (bid * 256 + threadIdx.x) >> 5;  // 0..4095
    int lane = threadIdx.x & 31;
    int j = gw >> 2;                            // output column 0..1023
    int s = gw & 3;                             // K chunk 0..3

    const int CHUNK4 = DIM / 4 / KSPLIT;        // 256 float4
    const float4* wrow = (const float4*)(Wup + (size_t)j * DIM) + s * CHUNK4;
    const float4* e4   = (const float4*)emb + s * CHUNK4;

    float acc[B];
#pragma unroll
    for (int b = 0; b < B; b++) acc[b] = 0.f;

#pragma unroll
    for (int k = 0; k < CHUNK4 / 32; k++) {     // 8 iters, fully unrolled
        int c = k * 32 + lane;
        float4 w = __ldg(&wrow[c]);
#pragma unroll
        for (int b = 0; b < B; b++) {
            float4 e = __ldg(&e4[b * (DIM / 4) + c]);
            acc[b] += e.x * w.x + e.y * w.y + e.z * w.z + e.w * w.w;
        }
    }
#pragma unroll
    for (int b = 0; b < B; b++) {
#pragma unroll
        for (int off = 16; off > 0; off >>= 1)
            acc[b] += __shfl_down_sync(0xffffffffu, acc[b], off);
    }
    if (lane == 0) {
#pragma unroll
        for (int b = 0; b < B; b++) g_xp[s][b * UP_OUT + j] = acc[b];
    }
}

// ---------------------------------------------------------------------------
// Kernel 2: down GEMV, full 4096 columns (512 blocks — do NOT shrink, R4
// showed small grids are latency-bound). W_down rows now hit L2.
// y[b,o] = sum_i val[b,i]*W_down[o,i], val[b,i] = x[b, ((i>>9)<<7)|(i&127)].
// ---------------------------------------------------------------------------
__global__ __launch_bounds__(256) void down_gemv(const float* __restrict__ Wdown) {
    __shared__ float sx[B * UP_OUT];            // 32 KB: sum of 4 up partials
    {
        float4* dst = (float4*)sx;
        for (int i = threadIdx.x; i < B * UP_OUT / 4; i += 256) {
            float4 a = __ldg((const float4*)g_xp[0] + i);
            float4 b = __ldg((const float4*)g_xp[1] + i);
            float4 c = __ldg((const float4*)g_xp[2] + i);
            float4 d = __ldg((const float4*)g_xp[3] + i);
            float4 r;
            r.x = (a.x + b.x) + (c.x + d.x);
            r.y = (a.y + b.y) + (c.y + d.y);
            r.z = (a.z + b.z) + (c.z + d.z);
            r.w = (a.w + b.w) + (c.w + d.w);
            dst[i] = r;
        }
    }
    __syncthreads();

    int warp = (blockIdx.x * 256 + threadIdx.x) >> 5;  // 0..4095
    int lane = threadIdx.x & 31;

    const float4* wrow = (const float4*)(Wdown + (size_t)warp * DIM);
    float acc[B];
#pragma unroll
    for (int b = 0; b < B; b++) acc[b] = 0.f;

#pragma unroll 8
    for (int c = lane; c < DIM / 4; c += 32) {
        float4 w = __ldg(&wrow[c]);
        int i  = c * 4;
        int xi = ((i >> 9) << 7) | (i & 127);   // head -> kv head
#pragma unroll
        for (int b = 0; b < B; b++) {
            float4 v = *(const float4*)(sx + b * UP_OUT + xi);
            acc[b] += v.x * w.x + v.y * w.y + v.z * w.z + v.w * w.w;
        }
    }
#pragma unroll
    for (int b = 0; b < B; b++) {
#pragma unroll
        for (int off = 16; off > 0; off >>= 1)
            acc[b] += __shfl_down_sync(0xffffffffu, acc[b], off);
    }
    if (lane == 0) {
#pragma unroll
        for (int b = 0; b < B; b++) g_y[b * DIM + warp] = acc[b];
    }
}

// ---------------------------------------------------------------------------
// Kernel 3: broadcast (proven 42 us / ~store ceiling). One block per token;
// streaming stores. seqlen prefix scan folded in; handles int32 OR int64.
// ---------------------------------------------------------------------------
__global__ __launch_bounds__(256) void broadcast_rows(float4* __restrict__ out,
                                                      const void* __restrict__ seqlen_raw,
                                                      int total_tokens) {
    __shared__ int sb;
    if (threadIdx.x == 0) {
        const int*       s32 = (const int*)seqlen_raw;
        const long long* s64 = (const long long*)seqlen_raw;
        long long sum64 = 0;
#pragma unroll
        for (int i = 0; i < B; i++) sum64 += s64[i];
        bool use64 = (sum64 == (long long)total_tokens);
        int t = blockIdx.x;
        int acc = 0, b = 0;
#pragma unroll
        for (int i = 0; i < B; i++) {
            int len = use64 ? (int)s64[i] : s32[i];
            if (t >= acc + len) b = i + 1;
            acc += len;
        }
        sb = (b < B) ? b : (B - 1);
    }
    __syncthreads();

    const float4* yrow = (const float4*)(g_y + (size_t)sb * DIM);
    float4*       orow = out + (size_t)blockIdx.x * (DIM / 4);
#pragma unroll
    for (int c = threadIdx.x; c < DIM / 4; c += 256)
        __stcs(&orow[c], __ldg(&yrow[c]));
}

// ---------------------------------------------------------------------------
extern "C" void kernel_launch(void* const* d_in, const int* in_sizes, int n_in,
                              void* d_out, int out_size) {
    const float* emb   = (const float*)d_in[0];  // [8, 4096]
    const float* Wup   = (const float*)d_in[1];  // [1024, 4096]
    const float* Wdown = (const float*)d_in[2];  // [4096, 4096]
    const void*  seql  = d_in[3];                // [8] int32 or int64

    int total_tokens = out_size / DIM;           // 16384

    up_gemv_pref<<<UP_BLOCKS + PREF_BLOCKS, 256>>>(emb, Wup, Wdown);
    down_gemv<<<DIM / 8, 256>>>(Wdown);          // 512 blocks, 4096 warps
    broadcast_rows<<<total_tokens, 256>>>((float4*)d_out, seql, total_tokens);
}

// round 6
// speedup vs baseline: 1.5566x; 1.0017x over previous
#include <cuda_runtime.h>
#include <cuda_bf16.h>
#include <cstdint>

#define DIM        4096
#define B          8
#define UP_OUT     1024               // N_KV * HEAD_DIM
#define KSPLIT     4                  // K-chunks for up-projection

#define UP_BLOCKS   512               // compute blocks in kernel 1
#define PREF_BLOCKS 2048              // prefetch blocks: 2048 x 32 KB = all of W_down

// Scratch (allocation-free rule: __device__ globals)
__device__ float g_xp[KSPLIT][B * UP_OUT]; // up partials [4][8,1024]
__device__ float g_y[B * DIM];             // down result [8,4096]

// ---------------------------------------------------------------------------
// Kernel 1: up GEMV (K-split partials, fully unrolled) + full W_down L2
// prefetch riding in extra blocks. up is latency-bound (DRAM 17% in R3), so
// the prefetch uses otherwise-idle bandwidth; W_down (67 MB) fits in L2
// (~126 MB), making the following down kernel L2-resident.
// Blocks [0,512): compute. Blocks [512,2560): prefetch.
// ---------------------------------------------------------------------------
__global__ __launch_bounds__(256) void up_gemv_pref(const float* __restrict__ emb,
                                                    const float* __restrict__ Wup,
                                                    const float* __restrict__ Wdown) {
    int bid = blockIdx.x;
    if (bid >= UP_BLOCKS) {
        // Pure L2-fill: 256 threads x 8 float4 = 32 KB per block.
        const float4* p = (const float4*)Wdown + (size_t)(bid - UP_BLOCKS) * 2048;
        float s = 0.f;
#pragma unroll
        for (int i = 0; i < 8; i++) {
            float4 v = __ldg(p + i * 256 + threadIdx.x);
            s += v.x + v.y + v.z + v.w;
        }
        asm volatile("" :: "f"(s));   // keep loads live
        return;
    }

    int gw   = (bid * 256 + threadIdx.x) >> 5;  // 0..4095
    int lane = threadIdx.x & 31;
    int j = gw >> 2;                            // output column 0..1023
    int s = gw & 3;                             // K chunk 0..3

    const int CHUNK4 = DIM / 4 / KSPLIT;        // 256 float4
    const float4* wrow = (const float4*)(Wup + (size_t)j * DIM) + s * CHUNK4;
    const float4* e4   = (const float4*)emb + s * CHUNK4;

    float acc[B];
#pragma unroll
    for (int b = 0; b < B; b++) acc[b] = 0.f;

#pragma unroll
    for (int k = 0; k < CHUNK4 / 32; k++) {     // 8 iters, fully unrolled
        int c = k * 32 + lane;
        float4 w = __ldg(&wrow[c]);
#pragma unroll
        for (int b = 0; b < B; b++) {
            float4 e = __ldg(&e4[b * (DIM / 4) + c]);
            acc[b] += e.x * w.x + e.y * w.y + e.z * w.z + e.w * w.w;
        }
    }
#pragma unroll
    for (int b = 0; b < B; b++) {
#pragma unroll
        for (int off = 16; off > 0; off >>= 1)
            acc[b] += __shfl_down_sync(0xffffffffu, acc[b], off);
    }
    if (lane == 0) {
#pragma unroll
        for (int b = 0; b < B; b++) g_xp[s][b * UP_OUT + j] = acc[b];
    }
}

// ---------------------------------------------------------------------------
// Kernel 2: down GEMV, full 4096 columns (512 blocks — do NOT shrink, R4
// showed small grids are latency-bound). W_down rows now hit L2.
// y[b,o] = sum_i val[b,i]*W_down[o,i], val[b,i] = x[b, ((i>>9)<<7)|(i&127)].
// ---------------------------------------------------------------------------
__global__ __launch_bounds__(256) void down_gemv(const float* __restrict__ Wdown) {
    __shared__ float sx[B * UP_OUT];            // 32 KB: sum of 4 up partials
    {
        float4* dst = (float4*)sx;
        for (int i = threadIdx.x; i < B * UP_OUT / 4; i += 256) {
            float4 a = __ldg((const float4*)g_xp[0] + i);
            float4 b = __ldg((const float4*)g_xp[1] + i);
            float4 c = __ldg((const float4*)g_xp[2] + i);
            float4 d = __ldg((const float4*)g_xp[3] + i);
            float4 r;
            r.x = (a.x + b.x) + (c.x + d.x);
            r.y = (a.y + b.y) + (c.y + d.y);
            r.z = (a.z + b.z) + (c.z + d.z);
            r.w = (a.w + b.w) + (c.w + d.w);
            dst[i] = r;
        }
    }
    __syncthreads();

    int warp = (blockIdx.x * 256 + threadIdx.x) >> 5;  // 0..4095
    int lane = threadIdx.x & 31;

    const float4* wrow = (const float4*)(Wdown + (size_t)warp * DIM);
    float acc[B];
#pragma unroll
    for (int b = 0; b < B; b++) acc[b] = 0.f;

#pragma unroll 8
    for (int c = lane; c < DIM / 4; c += 32) {
        float4 w = __ldg(&wrow[c]);
        int i  = c * 4;
        int xi = ((i >> 9) << 7) | (i & 127);   // head -> kv head
#pragma unroll
        for (int b = 0; b < B; b++) {
            float4 v = *(const float4*)(sx + b * UP_OUT + xi);
            acc[b] += v.x * w.x + v.y * w.y + v.z * w.z + v.w * w.w;
        }
    }
#pragma unroll
    for (int b = 0; b < B; b++) {
#pragma unroll
        for (int off = 16; off > 0; off >>= 1)
            acc[b] += __shfl_down_sync(0xffffffffu, acc[b], off);
    }
    if (lane == 0) {
#pragma unroll
        for (int b = 0; b < B; b++) g_y[b * DIM + warp] = acc[b];
    }
}

// ---------------------------------------------------------------------------
// Kernel 3: broadcast (proven 42 us / ~store ceiling). One block per token;
// streaming stores. seqlen prefix scan folded in; handles int32 OR int64.
// ---------------------------------------------------------------------------
__global__ __launch_bounds__(256) void broadcast_rows(float4* __restrict__ out,
                                                      const void* __restrict__ seqlen_raw,
                                                      int total_tokens) {
    __shared__ int sb;
    if (threadIdx.x == 0) {
        const int*       s32 = (const int*)seqlen_raw;
        const long long* s64 = (const long long*)seqlen_raw;
        long long sum64 = 0;
#pragma unroll
        for (int i = 0; i < B; i++) sum64 += s64[i];
        bool use64 = (sum64 == (long long)total_tokens);
        int t = blockIdx.x;
        int acc = 0, b = 0;
#pragma unroll
        for (int i = 0; i < B; i++) {
            int len = use64 ? (int)s64[i] : s32[i];
            if (t >= acc + len) b = i + 1;
            acc += len;
        }
        sb = (b < B) ? b : (B - 1);
    }
    __syncthreads();

    const float4* yrow = (const float4*)(g_y + (size_t)sb * DIM);
    float4*       orow = out + (size_t)blockIdx.x * (DIM / 4);
#pragma unroll
    for (int c = threadIdx.x; c < DIM / 4; c += 256)
        __stcs(&orow[c], __ldg(&yrow[c]));
}

// ---------------------------------------------------------------------------
extern "C" void kernel_launch(void* const* d_in, const int* in_sizes, int n_in,
                              void* d_out, int out_size) {
    const float* emb   = (const float*)d_in[0];  // [8, 4096]
    const float* Wup   = (const float*)d_in[1];  // [1024, 4096]
    const float* Wdown = (const float*)d_in[2];  // [4096, 4096]
    const void*  seql  = d_in[3];                // [8] int32 or int64

    int total_tokens = out_size / DIM;           // 16384

    up_gemv_pref<<<UP_BLOCKS + PREF_BLOCKS, 256>>>(emb, Wup, Wdown);
    down_gemv<<<DIM / 8, 256>>>(Wdown);          // 512 blocks, 4096 warps
    broadcast_rows<<<total_tokens, 256>>>((float4*)d_out, seql, total_tokens);
}